// round 16
// baseline (speedup 1.0000x reference)
#include <cuda_runtime.h>

typedef unsigned long long ull;

// Problem constants
constexpr int T_ = 30;
constexpr int BT = 128;    // batch elements per block (64 per group)
constexpr int NT = 512;    // threads per block (2 groups of 256)
constexpr int NBLK = 32768 / BT;  // 256

// XG scratch: per-block, per-thread dec1 input-preactivation tile (const over t).
__device__ ulonglong2 g_xg[NBLK][16][NT];

// ---------------- SMEM layout (floats) ----------------
constexpr int S_H1A = 0;        // 64*128
constexpr int S_H1B = 8192;     // 64*128
constexpr int S_H2A = 16384;    // 32*128
constexpr int S_H2B = 20480;    // 32*128
constexpr int S_HD2A = 24576;   // 4*128
constexpr int S_HD2B = 25088;   // 4*128
constexpr int S_XSA = 25600;    // 4*128 (x staging, parity A)
constexpr int S_XSB = 26112;    // 4*128 (x staging, parity B)
constexpr int S_B1  = 26624;    // 256
constexpr int S_B2  = 26880;    // 128
constexpr int S_BD1 = 27008;    // 256
constexpr int S_BD2 = 27264;    // 16 (+pad)
constexpr int S_W   = 27328;
// encode weights
constexpr int S_W1H = S_W;              // [64][256]
constexpr int S_W1X = S_W + 16384;      // [4][256]
constexpr int S_W2X = S_W1X + 1024;     // [64][128]
constexpr int S_W2H = S_W2X + 8192;     // [32][128]
constexpr int SMEM_FLOATS = S_W2H + 4096;  // 57024
// decode weights (overlay; ends well before SMEM_FLOATS)
constexpr int S_WD1H = S_W;             // [64][256]            -> 43712
constexpr int S_WD1X = S_W + 16384;     // [32][256]            -> 51904
constexpr int S_WD2XD = S_WD1X + 8192;  // [64][32] DUPLICATED  -> 53952
constexpr int S_WD2HD = S_WD2XD + 2048; // [4][32] DUPLICATED   -> 54080
constexpr int S_BD2D  = S_WD2HD + 128;  // [32] DUPLICATED bias -> 54112
constexpr int SMEM_BYTES = SMEM_FLOATS * 4;  // 228096 (unchanged)

// ---------------- packed f32x2 helpers ----------------
__device__ __forceinline__ ull ffma2(ull a, ull b, ull c) {
    ull d;
    asm("fma.rn.f32x2 %0, %1, %2, %3;" : "=l"(d) : "l"(a), "l"(b), "l"(c));
    return d;
}
__device__ __forceinline__ ull dup2(float x) {
    ull d; asm("mov.b64 %0, {%1, %1};" : "=l"(d) : "f"(x)); return d;
}
__device__ __forceinline__ float2 unpack2(ull v) {
    float2 f; asm("mov.b64 {%0, %1}, %2;" : "=f"(f.x), "=f"(f.y) : "l"(v)); return f;
}
__device__ __forceinline__ ull pack2(float x, float y) {
    ull v; asm("mov.b64 %0, {%1, %2};" : "=l"(v) : "f"(x), "f"(y)); return v;
}

// ---------------- activations (MUFU.TANH based) ----------------
__device__ __forceinline__ float tanha(float x) {
    float y; asm("tanh.approx.f32 %0, %1;" : "=f"(y) : "f"(x)); return y;
}
__device__ __forceinline__ float sigf(float x) {
    return fmaf(tanha(0.5f * x), 0.5f, 0.5f);
}
__device__ __forceinline__ void cell(float pi, float pf, float pg, float po,
                                     float &c, float &h) {
    c = sigf(pf) * c + sigf(pi) * tanha(pg);
    h = sigf(po) * tanha(c);
}

// W[4*HID][K] row-major -> smem transposed + gate-permuted
__device__ __forceinline__ void load_w_perm(const float* __restrict__ g,
                                            float* __restrict__ s,
                                            int HID, int K, int tid) {
    int n = 4 * HID * K;
    int FG = 4 * HID;
    for (int idx = tid; idx < n; idx += NT) {
        int gr = idx / K;
        int j = idx - gr * K;
        int gp = 4 * (gr % HID) + (gr / HID);
        s[j * FG + gp] = g[idx];
    }
}

extern __shared__ float sm[];

// 4-row sub-step
__device__ __forceinline__ void fma4(ull (*acc)[4], int o, const float4 wv,
                                     ulonglong2 hA, ulonglong2 hB) {
    ull w0 = dup2(wv.x), w1 = dup2(wv.y), w2 = dup2(wv.z), w3 = dup2(wv.w);
    acc[o + 0][0] = ffma2(w0, hA.x, acc[o + 0][0]);
    acc[o + 0][1] = ffma2(w0, hA.y, acc[o + 0][1]);
    acc[o + 0][2] = ffma2(w0, hB.x, acc[o + 0][2]);
    acc[o + 0][3] = ffma2(w0, hB.y, acc[o + 0][3]);
    acc[o + 1][0] = ffma2(w1, hA.x, acc[o + 1][0]);
    acc[o + 1][1] = ffma2(w1, hA.y, acc[o + 1][1]);
    acc[o + 1][2] = ffma2(w1, hB.x, acc[o + 1][2]);
    acc[o + 1][3] = ffma2(w1, hB.y, acc[o + 1][3]);
    acc[o + 2][0] = ffma2(w2, hA.x, acc[o + 2][0]);
    acc[o + 2][1] = ffma2(w2, hA.y, acc[o + 2][1]);
    acc[o + 2][2] = ffma2(w2, hB.x, acc[o + 2][2]);
    acc[o + 2][3] = ffma2(w2, hB.y, acc[o + 2][3]);
    acc[o + 3][0] = ffma2(w3, hA.x, acc[o + 3][0]);
    acc[o + 3][1] = ffma2(w3, hA.y, acc[o + 3][1]);
    acc[o + 3][2] = ffma2(w3, hB.x, acc[o + 3][2]);
    acc[o + 3][3] = ffma2(w3, hB.y, acc[o + 3][3]);
}

template <int NR4>
__device__ __forceinline__ void gemm_step(ull (*acc)[4],
                                          const float* __restrict__ wrow,
                                          const float* __restrict__ hbase) {
    const ulonglong2* hv2 = reinterpret_cast<const ulonglong2*>(hbase);
    ulonglong2 hA = hv2[0], hB = hv2[1];
    float4 wv0 = *reinterpret_cast<const float4*>(wrow);
    fma4(acc, 0, wv0, hA, hB);
    if (NR4 == 2) {
        float4 wv1 = *reinterpret_cast<const float4*>(wrow + 4);
        fma4(acc, 4, wv1, hA, hB);
    }
}

// 8-gate x 8-batch cell update + dup-free store of h rows
__device__ __forceinline__ void cell_store8(ull (*acc)[4], ull (*cst)[4],
                                            float* __restrict__ hdst, int gx, int b0) {
#pragma unroll
    for (int a = 0; a < 2; a++) {
        const int k = 2 * gx + a;
        ulonglong2 s0, s1;
#pragma unroll
        for (int p = 0; p < 4; p++) {
            float2 pi = unpack2(acc[4 * a + 0][p]);
            float2 pf = unpack2(acc[4 * a + 1][p]);
            float2 pg = unpack2(acc[4 * a + 2][p]);
            float2 po = unpack2(acc[4 * a + 3][p]);
            float2 cc = unpack2(cst[a][p]);
            float hx, hy;
            cell(pi.x, pf.x, pg.x, po.x, cc.x, hx);
            cell(pi.y, pf.y, pg.y, po.y, cc.y, hy);
            cst[a][p] = pack2(cc.x, cc.y);
            ull hv = pack2(hx, hy);
            if (p == 0) s0.x = hv; else if (p == 1) s0.y = hv;
            else if (p == 2) s1.x = hv; else s1.y = hv;
        }
        ulonglong2* dst = reinterpret_cast<ulonglong2*>(hdst + k * 128 + b0);
        dst[0] = s0; dst[1] = s1;
    }
}

__global__ __launch_bounds__(NT, 1)
void lstm_ae_kernel(const float* __restrict__ x,
                    const float* __restrict__ e1_Wih, const float* __restrict__ e1_Whh,
                    const float* __restrict__ e1_bih, const float* __restrict__ e1_bhh,
                    const float* __restrict__ e2_Wih, const float* __restrict__ e2_Whh,
                    const float* __restrict__ e2_bih, const float* __restrict__ e2_bhh,
                    const float* __restrict__ d1_Wih, const float* __restrict__ d1_Whh,
                    const float* __restrict__ d1_bih, const float* __restrict__ d1_bhh,
                    const float* __restrict__ d2_Wih, const float* __restrict__ d2_Whh,
                    const float* __restrict__ d2_bih, const float* __restrict__ d2_bhh,
                    float* __restrict__ out) {
    const int tid = threadIdx.x;
    const int base = blockIdx.x * BT;

    // ---- load encode weights ----
    load_w_perm(e1_Whh, sm + S_W1H, 64, 64, tid);
    load_w_perm(e1_Wih, sm + S_W1X, 64, 4, tid);
    load_w_perm(e2_Wih, sm + S_W2X, 32, 64, tid);
    load_w_perm(e2_Whh, sm + S_W2H, 32, 32, tid);
    if (tid < 256) {
        int g = tid, gp = 4 * (g % 64) + g / 64;
        sm[S_B1 + gp] = e1_bih[g] + e1_bhh[g];
    }
    if (tid >= 256 && tid < 384) {
        int g = tid - 256, gp = 4 * (g % 32) + g / 32;
        sm[S_B2 + gp] = e2_bih[g] + e2_bhh[g];
    }
    for (int i = tid; i < 8192; i += NT) sm[S_H1A + i] = 0.f;
    for (int i = tid; i < 4096; i += NT) sm[S_H2A + i] = 0.f;

    // group decomposition: grp 0 -> batch [0,64), grp 1 -> [64,128)
    const int grp = tid >> 8;
    const int tg = tid & 255;
    const int lane = tid & 31;
    const int w8 = tg >> 5;   // warp within group 0..7
    // lane map: bits[1:0]=bx_lo, bit2=gx_lo, bit3=bx_hi, bit4=gx_hi
    const int gx = w8 * 4 + ((((lane >> 4) & 1) << 1) | ((lane >> 2) & 1)); // 0..31
    const int bx = (((lane >> 3) & 1) << 2) | (lane & 3);                    // 0..7
    const int b0 = grp * 64 + bx * 8;
    const int g0a = gx * 8;
    const int g0b = gx * 4;
    // x-stage mapping
    const int xi = tg & 3;
    const int xb = grp * 64 + (tg >> 2);

    // stage x(0) into parity-A buffer
    sm[S_XSA + xi * 128 + xb] = x[(base + xb) * (T_ * 4) + 0 * 4 + xi];

    ull c1[2][4], c2st[1][4];
#pragma unroll
    for (int a = 0; a < 2; a++)
#pragma unroll
        for (int p = 0; p < 4; p++) c1[a][p] = 0ull;
#pragma unroll
    for (int p = 0; p < 4; p++) c2st[0][p] = 0ull;

    __syncthreads();

#define BARG() asm volatile("bar.sync %0, 256;" :: "r"(1 + grp) : "memory")

    // =================== ENCODE ===================
    // Single barrier per step (ordering proof in R12 commit).
    for (int t = 0; t < T_; t++) {
        const int pc = t & 1, pn = pc ^ 1;
        float* H1c = sm + (pc ? S_H1B : S_H1A);
        float* H1n = sm + (pn ? S_H1B : S_H1A);
        float* H2c = sm + (pc ? S_H2B : S_H2A);
        float* H2n = sm + (pn ? S_H2B : S_H2A);
        const float* XSc = sm + (pc ? S_XSB : S_XSA);
        float* XSn = sm + (pn ? S_XSB : S_XSA);

        // prefetch x(t+1) early (LDG latency covered by enc1 GEMM)
        float xval = 0.f;
        if (t + 1 < T_) xval = x[(base + xb) * (T_ * 4) + (t + 1) * 4 + xi];

        // ---- enc1 GEMM: b1 + W1x@x[pc] + W1h@h1[c] ----
        ull acc[8][4];
#pragma unroll
        for (int r = 0; r < 8; r++) {
            ull bb = dup2(sm[S_B1 + g0a + r]);
            acc[r][0] = bb; acc[r][1] = bb; acc[r][2] = bb; acc[r][3] = bb;
        }
#pragma unroll
        for (int i = 0; i < 4; i++)
            gemm_step<2>(acc, sm + S_W1X + i * 256 + g0a, XSc + i * 128 + b0);
#pragma unroll 4
        for (int j = 0; j < 64; j++)
            gemm_step<2>(acc, sm + S_W1H + j * 256 + g0a, H1c + j * 128 + b0);

        // ---- stage x(t+1) to other parity + enc1 cell (writes h1[n]) ----
        if (t + 1 < T_) XSn[xi * 128 + xb] = xval;
        cell_store8(acc, c1, H1n, gx, b0);
        BARG();

        // ---- enc2 GEMM: b2 + W2x@h1[n] + W2h@h2[c] ----
        ull a2[4][4];
#pragma unroll
        for (int r = 0; r < 4; r++) {
            ull bb = dup2(sm[S_B2 + g0b + r]);
            a2[r][0] = bb; a2[r][1] = bb; a2[r][2] = bb; a2[r][3] = bb;
        }
#pragma unroll 4
        for (int j = 0; j < 64; j++)
            gemm_step<1>(a2, sm + S_W2X + j * 128 + g0b, H1n + j * 128 + b0);
#pragma unroll 4
        for (int j = 0; j < 32; j++)
            gemm_step<1>(a2, sm + S_W2H + j * 128 + g0b, H2c + j * 128 + b0);

        // ---- enc2 cell: writes h2[n]; NO trailing barrier ----
        {
            ulonglong2 s0, s1;
#pragma unroll
            for (int p = 0; p < 4; p++) {
                float2 pi = unpack2(a2[0][p]);
                float2 pf = unpack2(a2[1][p]);
                float2 pg = unpack2(a2[2][p]);
                float2 po = unpack2(a2[3][p]);
                float2 cc = unpack2(c2st[0][p]);
                float hx, hy;
                cell(pi.x, pf.x, pg.x, po.x, cc.x, hx);
                cell(pi.y, pf.y, pg.y, po.y, cc.y, hy);
                c2st[0][p] = pack2(cc.x, cc.y);
                ull hv = pack2(hx, hy);
                if (p == 0) s0.x = hv; else if (p == 1) s0.y = hv;
                else if (p == 2) s1.x = hv; else s1.y = hv;
            }
            ulonglong2* dst = reinterpret_cast<ulonglong2*>(H2n + gx * 128 + b0);
            dst[0] = s0; dst[1] = s1;
        }
    }
    // latent = H2A (write of step 29 went to parity (29+1)&1 = 0)

    __syncthreads();

    // ---- load decode weights (overlay) + reset state ----
    load_w_perm(d1_Whh, sm + S_WD1H, 64, 64, tid);
    load_w_perm(d1_Wih, sm + S_WD1X, 64, 32, tid);
    // dec2 weights stored DUPLICATED: [j][2*gp] = [j][2*gp+1] = W[g][j]
    for (int idx = tid; idx < 16 * 64; idx += NT) {
        int g = idx / 64, j = idx - g * 64;
        int gp = 4 * (g % 4) + g / 4;
        float v = d2_Wih[idx];
        sm[S_WD2XD + j * 32 + 2 * gp] = v;
        sm[S_WD2XD + j * 32 + 2 * gp + 1] = v;
    }
    for (int idx = tid; idx < 16 * 4; idx += NT) {
        int g = idx / 4, j = idx - g * 4;
        int gp = 4 * (g % 4) + g / 4;
        float v = d2_Whh[idx];
        sm[S_WD2HD + j * 32 + 2 * gp] = v;
        sm[S_WD2HD + j * 32 + 2 * gp + 1] = v;
    }
    if (tid < 256) {
        int g = tid, gp = 4 * (g % 64) + g / 64;
        sm[S_BD1 + gp] = d1_bih[g] + d1_bhh[g];
    }
    if (tid >= 256 && tid < 272) {
        int g = tid - 256, gp = 4 * (g % 4) + g / 4;
        float v = d2_bih[g] + d2_bhh[g];
        sm[S_BD2D + 2 * gp] = v;
        sm[S_BD2D + 2 * gp + 1] = v;
    }
    for (int i = tid; i < 8192; i += NT) sm[S_H1A + i] = 0.f;   // hd1[0] = 0
    for (int i = tid; i < 512; i += NT) sm[S_HD2A + i] = 0.f;   // hd2[0] = 0
#pragma unroll
    for (int a = 0; a < 2; a++)
#pragma unroll
        for (int p = 0; p < 4; p++) c1[a][p] = 0ull;
    // dec2 packed mapping: active threads tg<128 own (k, batch pair)
    const int dk = tg & 3;            // gate cell 0..3
    const int db = grp * 64 + ((tg >> 2) & 31) * 2;  // batch pair base
    ull cd2p = 0ull;                  // packed c-state for 2 batches
    __syncthreads();

    // ---- XG precompute: bd1 + Wd1x@latent (constant over t) -> global scratch.
    // Same summation order as inline, so output is bit-exact. Own tile only.
    {
        ull acc[8][4];
#pragma unroll
        for (int r = 0; r < 8; r++) {
            ull bb = dup2(sm[S_BD1 + g0a + r]);
            acc[r][0] = bb; acc[r][1] = bb; acc[r][2] = bb; acc[r][3] = bb;
        }
#pragma unroll 4
        for (int j = 0; j < 32; j++)
            gemm_step<2>(acc, sm + S_WD1X + j * 256 + g0a, sm + S_H2A + j * 128 + b0);
        ulonglong2* xgp = &g_xg[blockIdx.x][0][tid];
#pragma unroll
        for (int r = 0; r < 8; r++) {
            xgp[(2 * r + 0) * NT] = make_ulonglong2(acc[r][0], acc[r][1]);
            xgp[(2 * r + 1) * NT] = make_ulonglong2(acc[r][2], acc[r][3]);
        }
    }

    // =================== DECODE ===================
    // Single barrier per step (proof in R11 commit). dec2 is f32x2-packed:
    // 128 active threads per group (half), each owning (gate k, 2 batches);
    // the idle half falls straight through into the next dec1 GEMM.
    for (int t = 0; t < T_; t++) {
        const int pc = t & 1, pn = pc ^ 1;
        float* H1c = sm + (pc ? S_H1B : S_H1A);
        float* H1n = sm + (pn ? S_H1B : S_H1A);
        float* HDc = sm + (pc ? S_HD2B : S_HD2A);
        float* HDn = sm + (pn ? S_HD2B : S_HD2A);

        // ---- dec1 GEMM: acc = XG (L2 scratch) + Wd1h@hd1[c] ----
        ull acc[8][4];
        {
            const ulonglong2* xgp = &g_xg[blockIdx.x][0][tid];
#pragma unroll
            for (int r = 0; r < 8; r++) {
                ulonglong2 v0 = xgp[(2 * r + 0) * NT];
                ulonglong2 v1 = xgp[(2 * r + 1) * NT];
                acc[r][0] = v0.x; acc[r][1] = v0.y;
                acc[r][2] = v1.x; acc[r][3] = v1.y;
            }
        }
#pragma unroll 4
        for (int j = 0; j < 64; j++)
            gemm_step<2>(acc, sm + S_WD1H + j * 256 + g0a, H1c + j * 128 + b0);

        // ---- dec1 cell: writes hd1[n] ----
        cell_store8(acc, c1, H1n, gx, b0);
        BARG();

        // ---- dec2 (packed): tg<128 own (k=dk, batches db,db+1) ----
        if (tg < 128) {
            // biases pre-duplicated: (b0b0,b1b1),(b2b2,b3b3)
            const ulonglong2* bb = reinterpret_cast<const ulonglong2*>(sm + S_BD2D + 8 * dk);
            ulonglong2 bq0 = bb[0], bq1 = bb[1];
            ull a0 = bq0.x, a1 = bq0.y, a2v = bq1.x, a3 = bq1.y;
#pragma unroll 4
            for (int j = 0; j < 64; j++) {
                ull hv = *reinterpret_cast<const ull*>(H1n + j * 128 + db);
                const ulonglong2* wp = reinterpret_cast<const ulonglong2*>(sm + S_WD2XD + j * 32 + 8 * dk);
                ulonglong2 w01 = wp[0], w23 = wp[1];
                a0 = ffma2(w01.x, hv, a0);
                a1 = ffma2(w01.y, hv, a1);
                a2v = ffma2(w23.x, hv, a2v);
                a3 = ffma2(w23.y, hv, a3);
            }
#pragma unroll
            for (int j = 0; j < 4; j++) {
                ull hv = *reinterpret_cast<const ull*>(HDc + j * 128 + db);
                const ulonglong2* wp = reinterpret_cast<const ulonglong2*>(sm + S_WD2HD + j * 32 + 8 * dk);
                ulonglong2 w01 = wp[0], w23 = wp[1];
                a0 = ffma2(w01.x, hv, a0);
                a1 = ffma2(w01.y, hv, a1);
                a2v = ffma2(w23.x, hv, a2v);
                a3 = ffma2(w23.y, hv, a3);
            }
            float2 pi = unpack2(a0), pf = unpack2(a1), pg = unpack2(a2v), po = unpack2(a3);
            float2 cc = unpack2(cd2p);
            float hx, hy;
            cell(pi.x, pf.x, pg.x, po.x, cc.x, hx);
            cell(pi.y, pf.y, pg.y, po.y, cc.y, hy);
            cd2p = pack2(cc.x, cc.y);
            *reinterpret_cast<ull*>(HDn + dk * 128 + db) = pack2(hx, hy);
            out[(base + db) * (T_ * 4) + t * 4 + dk] = hx;
            out[(base + db + 1) * (T_ * 4) + t * 4 + dk] = hy;
        }
        // no trailing barrier: next BARG provides all ordering
    }
#undef BARG
}

extern "C" void kernel_launch(void* const* d_in, const int* in_sizes, int n_in,
                              void* d_out, int out_size) {
    cudaFuncSetAttribute(lstm_ae_kernel,
                         cudaFuncAttributeMaxDynamicSharedMemorySize, SMEM_BYTES);
    lstm_ae_kernel<<<NBLK, NT, SMEM_BYTES>>>(
        (const float*)d_in[0],
        (const float*)d_in[1], (const float*)d_in[2], (const float*)d_in[3], (const float*)d_in[4],
        (const float*)d_in[5], (const float*)d_in[6], (const float*)d_in[7], (const float*)d_in[8],
        (const float*)d_in[9], (const float*)d_in[10], (const float*)d_in[11], (const float*)d_in[12],
        (const float*)d_in[13], (const float*)d_in[14], (const float*)d_in[15], (const float*)d_in[16],
        (float*)d_out);
}

// round 17
// speedup vs baseline: 1.0332x; 1.0332x over previous
#include <cuda_runtime.h>

typedef unsigned long long ull;

// Problem constants
constexpr int T_ = 30;
constexpr int BT = 128;    // batch elements per block (64 per group)
constexpr int NT = 512;    // threads per block (2 groups of 256)
constexpr int NBLK = 32768 / BT;  // 256

// XG scratch: per-block, per-thread dec1 input-preactivation tile (const over t).
__device__ ulonglong2 g_xg[NBLK][16][NT];

// ---------------- SMEM layout (floats) ----------------
constexpr int S_H1A = 0;        // 64*128
constexpr int S_H1B = 8192;     // 64*128
constexpr int S_H2A = 16384;    // 32*128
constexpr int S_H2B = 20480;    // 32*128
constexpr int S_HD2A = 24576;   // 4*128
constexpr int S_HD2B = 25088;   // 4*128
constexpr int S_XSA = 25600;    // 4*128 (x staging, parity A)
constexpr int S_XSB = 26112;    // 4*128 (x staging, parity B)
constexpr int S_B1  = 26624;    // 256
constexpr int S_B2  = 26880;    // 128
constexpr int S_BD1 = 27008;    // 256
constexpr int S_BD2 = 27264;    // 16 (+pad)
constexpr int S_W   = 27328;
// encode weights
constexpr int S_W1H = S_W;              // [64][256]
constexpr int S_W1X = S_W + 16384;      // [4][256]
constexpr int S_W2X = S_W1X + 1024;     // [64][128]
constexpr int S_W2H = S_W2X + 8192;     // [32][128]
constexpr int SMEM_FLOATS = S_W2H + 4096;  // 57024
// decode weights (overlay)
constexpr int S_WD1H = S_W;             // [64][256]
constexpr int S_WD1X = S_W + 16384;     // [32][256]
constexpr int S_WD2X = S_WD1X + 8192;   // [64][16]
constexpr int S_WD2H = S_WD2X + 1024;   // [4][16]
constexpr int SMEM_BYTES = SMEM_FLOATS * 4;  // 228096

// ---------------- packed f32x2 helpers ----------------
__device__ __forceinline__ ull ffma2(ull a, ull b, ull c) {
    ull d;
    asm("fma.rn.f32x2 %0, %1, %2, %3;" : "=l"(d) : "l"(a), "l"(b), "l"(c));
    return d;
}
__device__ __forceinline__ ull dup2(float x) {
    ull d; asm("mov.b64 %0, {%1, %1};" : "=l"(d) : "f"(x)); return d;
}
__device__ __forceinline__ float2 unpack2(ull v) {
    float2 f; asm("mov.b64 {%0, %1}, %2;" : "=f"(f.x), "=f"(f.y) : "l"(v)); return f;
}
__device__ __forceinline__ ull pack2(float x, float y) {
    ull v; asm("mov.b64 %0, {%1, %2};" : "=l"(v) : "f"(x), "f"(y)); return v;
}

// ---------------- activations (MUFU.TANH based) ----------------
__device__ __forceinline__ float tanha(float x) {
    float y; asm("tanh.approx.f32 %0, %1;" : "=f"(y) : "f"(x)); return y;
}
__device__ __forceinline__ float sigf(float x) {
    return fmaf(tanha(0.5f * x), 0.5f, 0.5f);
}
__device__ __forceinline__ void cell(float pi, float pf, float pg, float po,
                                     float &c, float &h) {
    c = sigf(pf) * c + sigf(pi) * tanha(pg);
    h = sigf(po) * tanha(c);
}

// W[4*HID][K] row-major -> smem transposed + gate-permuted
__device__ __forceinline__ void load_w_perm(const float* __restrict__ g,
                                            float* __restrict__ s,
                                            int HID, int K, int tid) {
    int n = 4 * HID * K;
    int FG = 4 * HID;
    for (int idx = tid; idx < n; idx += NT) {
        int gr = idx / K;
        int j = idx - gr * K;
        int gp = 4 * (gr % HID) + (gr / HID);
        s[j * FG + gp] = g[idx];
    }
}

extern __shared__ float sm[];

// 4-row sub-step
__device__ __forceinline__ void fma4(ull (*acc)[4], int o, const float4 wv,
                                     ulonglong2 hA, ulonglong2 hB) {
    ull w0 = dup2(wv.x), w1 = dup2(wv.y), w2 = dup2(wv.z), w3 = dup2(wv.w);
    acc[o + 0][0] = ffma2(w0, hA.x, acc[o + 0][0]);
    acc[o + 0][1] = ffma2(w0, hA.y, acc[o + 0][1]);
    acc[o + 0][2] = ffma2(w0, hB.x, acc[o + 0][2]);
    acc[o + 0][3] = ffma2(w0, hB.y, acc[o + 0][3]);
    acc[o + 1][0] = ffma2(w1, hA.x, acc[o + 1][0]);
    acc[o + 1][1] = ffma2(w1, hA.y, acc[o + 1][1]);
    acc[o + 1][2] = ffma2(w1, hB.x, acc[o + 1][2]);
    acc[o + 1][3] = ffma2(w1, hB.y, acc[o + 1][3]);
    acc[o + 2][0] = ffma2(w2, hA.x, acc[o + 2][0]);
    acc[o + 2][1] = ffma2(w2, hA.y, acc[o + 2][1]);
    acc[o + 2][2] = ffma2(w2, hB.x, acc[o + 2][2]);
    acc[o + 2][3] = ffma2(w2, hB.y, acc[o + 2][3]);
    acc[o + 3][0] = ffma2(w3, hA.x, acc[o + 3][0]);
    acc[o + 3][1] = ffma2(w3, hA.y, acc[o + 3][1]);
    acc[o + 3][2] = ffma2(w3, hB.x, acc[o + 3][2]);
    acc[o + 3][3] = ffma2(w3, hB.y, acc[o + 3][3]);
}

template <int NR4>
__device__ __forceinline__ void gemm_step(ull (*acc)[4],
                                          const float* __restrict__ wrow,
                                          const float* __restrict__ hbase) {
    const ulonglong2* hv2 = reinterpret_cast<const ulonglong2*>(hbase);
    ulonglong2 hA = hv2[0], hB = hv2[1];
    float4 wv0 = *reinterpret_cast<const float4*>(wrow);
    fma4(acc, 0, wv0, hA, hB);
    if (NR4 == 2) {
        float4 wv1 = *reinterpret_cast<const float4*>(wrow + 4);
        fma4(acc, 4, wv1, hA, hB);
    }
}

// 8-gate x 8-batch cell update + dup-free store of h rows
__device__ __forceinline__ void cell_store8(ull (*acc)[4], ull (*cst)[4],
                                            float* __restrict__ hdst, int gx, int b0) {
#pragma unroll
    for (int a = 0; a < 2; a++) {
        const int k = 2 * gx + a;
        ulonglong2 s0, s1;
#pragma unroll
        for (int p = 0; p < 4; p++) {
            float2 pi = unpack2(acc[4 * a + 0][p]);
            float2 pf = unpack2(acc[4 * a + 1][p]);
            float2 pg = unpack2(acc[4 * a + 2][p]);
            float2 po = unpack2(acc[4 * a + 3][p]);
            float2 cc = unpack2(cst[a][p]);
            float hx, hy;
            cell(pi.x, pf.x, pg.x, po.x, cc.x, hx);
            cell(pi.y, pf.y, pg.y, po.y, cc.y, hy);
            cst[a][p] = pack2(cc.x, cc.y);
            ull hv = pack2(hx, hy);
            if (p == 0) s0.x = hv; else if (p == 1) s0.y = hv;
            else if (p == 2) s1.x = hv; else s1.y = hv;
        }
        ulonglong2* dst = reinterpret_cast<ulonglong2*>(hdst + k * 128 + b0);
        dst[0] = s0; dst[1] = s1;
    }
}

__global__ __launch_bounds__(NT, 1)
void lstm_ae_kernel(const float* __restrict__ x,
                    const float* __restrict__ e1_Wih, const float* __restrict__ e1_Whh,
                    const float* __restrict__ e1_bih, const float* __restrict__ e1_bhh,
                    const float* __restrict__ e2_Wih, const float* __restrict__ e2_Whh,
                    const float* __restrict__ e2_bih, const float* __restrict__ e2_bhh,
                    const float* __restrict__ d1_Wih, const float* __restrict__ d1_Whh,
                    const float* __restrict__ d1_bih, const float* __restrict__ d1_bhh,
                    const float* __restrict__ d2_Wih, const float* __restrict__ d2_Whh,
                    const float* __restrict__ d2_bih, const float* __restrict__ d2_bhh,
                    float* __restrict__ out) {
    const int tid = threadIdx.x;
    const int base = blockIdx.x * BT;

    // ---- load encode weights ----
    load_w_perm(e1_Whh, sm + S_W1H, 64, 64, tid);
    load_w_perm(e1_Wih, sm + S_W1X, 64, 4, tid);
    load_w_perm(e2_Wih, sm + S_W2X, 32, 64, tid);
    load_w_perm(e2_Whh, sm + S_W2H, 32, 32, tid);
    if (tid < 256) {
        int g = tid, gp = 4 * (g % 64) + g / 64;
        sm[S_B1 + gp] = e1_bih[g] + e1_bhh[g];
    }
    if (tid >= 256 && tid < 384) {
        int g = tid - 256, gp = 4 * (g % 32) + g / 32;
        sm[S_B2 + gp] = e2_bih[g] + e2_bhh[g];
    }
    for (int i = tid; i < 8192; i += NT) sm[S_H1A + i] = 0.f;
    for (int i = tid; i < 4096; i += NT) sm[S_H2A + i] = 0.f;

    // group decomposition: grp 0 -> batch [0,64), grp 1 -> [64,128)
    const int grp = tid >> 8;
    const int tg = tid & 255;
    const int lane = tid & 31;
    const int w8 = tg >> 5;   // warp within group 0..7
    // lane map: bits[1:0]=bx_lo, bit2=gx_lo, bit3=bx_hi, bit4=gx_hi
    const int gx = w8 * 4 + ((((lane >> 4) & 1) << 1) | ((lane >> 2) & 1)); // 0..31
    const int bx = (((lane >> 3) & 1) << 2) | (lane & 3);                    // 0..7
    const int b0 = grp * 64 + bx * 8;
    const int g0a = gx * 8;
    const int g0b = gx * 4;
    // dec2 / x-stage mapping
    const int xi = tg & 3;
    const int xb = grp * 64 + (tg >> 2);

    // stage x(0) into parity-A buffer
    sm[S_XSA + xi * 128 + xb] = x[(base + xb) * (T_ * 4) + 0 * 4 + xi];

    ull c1[2][4], c2st[1][4];
#pragma unroll
    for (int a = 0; a < 2; a++)
#pragma unroll
        for (int p = 0; p < 4; p++) c1[a][p] = 0ull;
#pragma unroll
    for (int p = 0; p < 4; p++) c2st[0][p] = 0ull;

    __syncthreads();

#define BARG() asm volatile("bar.sync %0, 256;" :: "r"(1 + grp) : "memory")

    // =================== ENCODE ===================
    // Single barrier per step (ordering proof in R12 commit).
    for (int t = 0; t < T_; t++) {
        const int pc = t & 1, pn = pc ^ 1;
        float* H1c = sm + (pc ? S_H1B : S_H1A);
        float* H1n = sm + (pn ? S_H1B : S_H1A);
        float* H2c = sm + (pc ? S_H2B : S_H2A);
        float* H2n = sm + (pn ? S_H2B : S_H2A);
        const float* XSc = sm + (pc ? S_XSB : S_XSA);
        float* XSn = sm + (pn ? S_XSB : S_XSA);

        // prefetch x(t+1) early (LDG latency covered by enc1 GEMM)
        float xval = 0.f;
        if (t + 1 < T_) xval = x[(base + xb) * (T_ * 4) + (t + 1) * 4 + xi];

        // ---- enc1 GEMM: b1 + W1x@x[pc] + W1h@h1[c] ----
        ull acc[8][4];
#pragma unroll
        for (int r = 0; r < 8; r++) {
            ull bb = dup2(sm[S_B1 + g0a + r]);
            acc[r][0] = bb; acc[r][1] = bb; acc[r][2] = bb; acc[r][3] = bb;
        }
#pragma unroll
        for (int i = 0; i < 4; i++)
            gemm_step<2>(acc, sm + S_W1X + i * 256 + g0a, XSc + i * 128 + b0);
#pragma unroll 8
        for (int j = 0; j < 64; j++)
            gemm_step<2>(acc, sm + S_W1H + j * 256 + g0a, H1c + j * 128 + b0);

        // ---- stage x(t+1) to other parity + enc1 cell (writes h1[n]) ----
        if (t + 1 < T_) XSn[xi * 128 + xb] = xval;
        cell_store8(acc, c1, H1n, gx, b0);
        BARG();

        // ---- enc2 GEMM: b2 + W2x@h1[n] + W2h@h2[c] ----
        ull a2[4][4];
#pragma unroll
        for (int r = 0; r < 4; r++) {
            ull bb = dup2(sm[S_B2 + g0b + r]);
            a2[r][0] = bb; a2[r][1] = bb; a2[r][2] = bb; a2[r][3] = bb;
        }
#pragma unroll 4
        for (int j = 0; j < 64; j++)
            gemm_step<1>(a2, sm + S_W2X + j * 128 + g0b, H1n + j * 128 + b0);
#pragma unroll 4
        for (int j = 0; j < 32; j++)
            gemm_step<1>(a2, sm + S_W2H + j * 128 + g0b, H2c + j * 128 + b0);

        // ---- enc2 cell: writes h2[n]; NO trailing barrier ----
        {
            ulonglong2 s0, s1;
#pragma unroll
            for (int p = 0; p < 4; p++) {
                float2 pi = unpack2(a2[0][p]);
                float2 pf = unpack2(a2[1][p]);
                float2 pg = unpack2(a2[2][p]);
                float2 po = unpack2(a2[3][p]);
                float2 cc = unpack2(c2st[0][p]);
                float hx, hy;
                cell(pi.x, pf.x, pg.x, po.x, cc.x, hx);
                cell(pi.y, pf.y, pg.y, po.y, cc.y, hy);
                c2st[0][p] = pack2(cc.x, cc.y);
                ull hv = pack2(hx, hy);
                if (p == 0) s0.x = hv; else if (p == 1) s0.y = hv;
                else if (p == 2) s1.x = hv; else s1.y = hv;
            }
            ulonglong2* dst = reinterpret_cast<ulonglong2*>(H2n + gx * 128 + b0);
            dst[0] = s0; dst[1] = s1;
        }
    }
    // latent = H2A (write of step 29 went to parity (29+1)&1 = 0)

    __syncthreads();

    // ---- load decode weights (overlay) + reset state ----
    load_w_perm(d1_Whh, sm + S_WD1H, 64, 64, tid);
    load_w_perm(d1_Wih, sm + S_WD1X, 64, 32, tid);
    load_w_perm(d2_Wih, sm + S_WD2X, 4, 64, tid);
    load_w_perm(d2_Whh, sm + S_WD2H, 4, 4, tid);
    if (tid < 256) {
        int g = tid, gp = 4 * (g % 64) + g / 64;
        sm[S_BD1 + gp] = d1_bih[g] + d1_bhh[g];
    }
    if (tid >= 256 && tid < 272) {
        int g = tid - 256, gp = 4 * (g % 4) + g / 4;
        sm[S_BD2 + gp] = d2_bih[g] + d2_bhh[g];
    }
    for (int i = tid; i < 8192; i += NT) sm[S_H1A + i] = 0.f;   // hd1[0] = 0
    for (int i = tid; i < 512; i += NT) sm[S_HD2A + i] = 0.f;   // hd2[0] = 0
#pragma unroll
    for (int a = 0; a < 2; a++)
#pragma unroll
        for (int p = 0; p < 4; p++) c1[a][p] = 0ull;
    float cd2 = 0.f;
    __syncthreads();

    // ---- XG precompute: bd1 + Wd1x@latent (constant over t) -> global scratch.
    // Same summation order as inline, so output is bit-exact. Own tile only.
    {
        ull acc[8][4];
#pragma unroll
        for (int r = 0; r < 8; r++) {
            ull bb = dup2(sm[S_BD1 + g0a + r]);
            acc[r][0] = bb; acc[r][1] = bb; acc[r][2] = bb; acc[r][3] = bb;
        }
#pragma unroll 4
        for (int j = 0; j < 32; j++)
            gemm_step<2>(acc, sm + S_WD1X + j * 256 + g0a, sm + S_H2A + j * 128 + b0);
        ulonglong2* xgp = &g_xg[blockIdx.x][0][tid];
#pragma unroll
        for (int r = 0; r < 8; r++) {
            xgp[(2 * r + 0) * NT] = make_ulonglong2(acc[r][0], acc[r][1]);
            xgp[(2 * r + 1) * NT] = make_ulonglong2(acc[r][2], acc[r][3]);
        }
    }

    // =================== DECODE ===================
    // Single barrier per step (proof in R11 commit). XG loaded at dec1-GEMM
    // top (R12 placement; R13's hold-across-barrier variant regressed).
    for (int t = 0; t < T_; t++) {
        const int pc = t & 1, pn = pc ^ 1;
        float* H1c = sm + (pc ? S_H1B : S_H1A);
        float* H1n = sm + (pn ? S_H1B : S_H1A);
        float* HDc = sm + (pc ? S_HD2B : S_HD2A);
        float* HDn = sm + (pn ? S_HD2B : S_HD2A);

        // ---- dec1 GEMM: acc = XG (L2 scratch) + Wd1h@hd1[c] ----
        ull acc[8][4];
        {
            const ulonglong2* xgp = &g_xg[blockIdx.x][0][tid];
#pragma unroll
            for (int r = 0; r < 8; r++) {
                ulonglong2 v0 = xgp[(2 * r + 0) * NT];
                ulonglong2 v1 = xgp[(2 * r + 1) * NT];
                acc[r][0] = v0.x; acc[r][1] = v0.y;
                acc[r][2] = v1.x; acc[r][3] = v1.y;
            }
        }
#pragma unroll 8
        for (int j = 0; j < 64; j++)
            gemm_step<2>(acc, sm + S_WD1H + j * 256 + g0a, H1c + j * 128 + b0);

        // ---- dec1 cell: writes hd1[n] ----
        cell_store8(acc, c1, H1n, gx, b0);
        BARG();

        // ---- dec2: every thread owns (k = xi, b = xb); no trailing barrier ----
        {
            const int k = xi;
            const int b = xb;
            const float4 bb = *reinterpret_cast<const float4*>(sm + S_BD2 + 4 * k);
            float a0 = bb.x, a1 = bb.y, a2v = bb.z, a3 = bb.w;
#pragma unroll 4
            for (int j = 0; j < 64; j++) {
                float hj = H1n[j * 128 + b];
                const float4 wv = *reinterpret_cast<const float4*>(sm + S_WD2X + j * 16 + 4 * k);
                a0 = fmaf(wv.x, hj, a0);
                a1 = fmaf(wv.y, hj, a1);
                a2v = fmaf(wv.z, hj, a2v);
                a3 = fmaf(wv.w, hj, a3);
            }
#pragma unroll
            for (int j = 0; j < 4; j++) {
                float hj = HDc[j * 128 + b];
                const float4 wv = *reinterpret_cast<const float4*>(sm + S_WD2H + j * 16 + 4 * k);
                a0 = fmaf(wv.x, hj, a0);
                a1 = fmaf(wv.y, hj, a1);
                a2v = fmaf(wv.z, hj, a2v);
                a3 = fmaf(wv.w, hj, a3);
            }
            float h;
            cell(a0, a1, a2v, a3, cd2, h);
            HDn[k * 128 + b] = h;
            out[(base + b) * (T_ * 4) + t * 4 + k] = h;
        }
    }
#undef BARG
}

extern "C" void kernel_launch(void* const* d_in, const int* in_sizes, int n_in,
                              void* d_out, int out_size) {
    cudaFuncSetAttribute(lstm_ae_kernel,
                         cudaFuncAttributeMaxDynamicSharedMemorySize, SMEM_BYTES);
    lstm_ae_kernel<<<NBLK, NT, SMEM_BYTES>>>(
        (const float*)d_in[0],
        (const float*)d_in[1], (const float*)d_in[2], (const float*)d_in[3], (const float*)d_in[4],
        (const float*)d_in[5], (const float*)d_in[6], (const float*)d_in[7], (const float*)d_in[8],
        (const float*)d_in[9], (const float*)d_in[10], (const float*)d_in[11], (const float*)d_in[12],
        (const float*)d_in[13], (const float*)d_in[14], (const float*)d_in[15], (const float*)d_in[16],
        (float*)d_out);
}